// round 12
// baseline (speedup 1.0000x reference)
#include <cuda_runtime.h>
#include <cuda_bf16.h>
#include <cstdint>

// LSTM seq2seq via mma.sync (HMMA bf16, portable sm_103):
//   gates[256, 64b] = W[256, 80] @ state[64b, 80]^T, hi/lo bf16 split (3 passes)
// R12: 16 warps (1 M-tile each), 3 independent accumulator chains per nt-group.

#define SRCLEN 7
#define PREDLEN 10
#define NSTEPS 17
#define IN_ 9
#define H_ 64
#define TPB 512
#define BPC 64          // batch rows per CTA
#define GRID 1024

// smem layout (bytes)
#define SB_SHI 0                         // state hi: 64 rows x 88 bf16 (176B)
#define SB_SLO 11264                     // state lo
#define SB_G   22528                     // gate buf: 256 rows x 68 f32 (272B)
#define SB_FCW (22528 + 69632)           // 92160: fc weights 9x64 f32
#define SB_FCB (SB_FCW + 2304)           // 94464
#define SB_P   (SB_FCB + 64)             // 94528: FC partials 64 x 72 f32
#define SMEM_BYTES (SB_P + 18432)        // 112960

typedef unsigned int u32;

__device__ __forceinline__ float fast_tanh(float x) {
    float y; asm("tanh.approx.f32 %0, %1;" : "=f"(y) : "f"(x)); return y;
}
__device__ __forceinline__ float fast_sigmoid(float x) { return fmaf(0.5f, fast_tanh(0.5f * x), 0.5f); }
__device__ __forceinline__ u32 pk(float a, float b) {
    __nv_bfloat162 t = __floats2bfloat162_rn(a, b); return *reinterpret_cast<u32*>(&t);
}
__device__ __forceinline__ float bfhi(float v) { return __bfloat162float(__float2bfloat16(v)); }
__device__ __forceinline__ void split2(float a, float b, u32 &hi, u32 &lo) {
    float ah = bfhi(a), bh = bfhi(b);
    hi = pk(a, b); lo = pk(a - ah, b - bh);
}

#define MMA4(d, a, b0, b1) asm volatile( \
    "mma.sync.aligned.m16n8k16.row.col.f32.bf16.bf16.f32 " \
    "{%0,%1,%2,%3},{%4,%5,%6,%7},{%8,%9},{%0,%1,%2,%3};" \
    : "+f"((d)[0]), "+f"((d)[1]), "+f"((d)[2]), "+f"((d)[3]) \
    : "r"((a)[0]), "r"((a)[1]), "r"((a)[2]), "r"((a)[3]), "r"(b0), "r"(b1))

// fused weight element: row m = 4j+g -> source row wr = g*64+j
__device__ __forceinline__ float welem(const float* __restrict__ Wih,
                                       const float* __restrict__ Whh,
                                       const float* __restrict__ bias, int m, int k) {
    int j = m >> 2, g = m & 3, wr = g * 64 + j;
    if (k < 64) return Whh[wr * 64 + k];
    if (k < 73) return Wih[wr * 9 + (k - 64)];
    if (k == 73) return bias[wr];
    return 0.0f;
}

// Per-warp A fragments for M-tile mt = wid: 5 K-chunks x 4 regs (hi + lo).
// m16n8k16 A frag: q0:(r,k0) q1:(r+8,k0) q2:(r,k0+8) q3:(r+8,k0+8);
// r = lane/4, k0 = 2*(lane%4), reg = 2 bf16 along k.
__device__ void load_A(u32 ah[5][4], u32 al[5][4],
                       const float* __restrict__ Wih, const float* __restrict__ Whh,
                       const float* __restrict__ bias, int wid, int lane) {
    int g4 = lane >> 2, t4 = lane & 3;
    #pragma unroll
    for (int kc = 0; kc < 5; kc++)
        #pragma unroll
        for (int q = 0; q < 4; q++) {
            int m = 16 * wid + g4 + (q & 1) * 8;
            int k = 16 * kc + 2 * t4 + (q >> 1) * 8;
            float v0 = welem(Wih, Whh, bias, m, k);
            float v1 = welem(Wih, Whh, bias, m, k + 1);
            split2(v0, v1, ah[kc][q], al[kc][q]);
        }
}

__global__ void __launch_bounds__(TPB, 1)
lstm_mma(const float* __restrict__ src,
         const float* __restrict__ eWih, const float* __restrict__ eWhh, const float* __restrict__ eb,
         const float* __restrict__ dWih, const float* __restrict__ dWhh, const float* __restrict__ db,
         const float* __restrict__ fcW, const float* __restrict__ fcb, float* __restrict__ out)
{
    extern __shared__ char sm[];
    const int tid = threadIdx.x;
    const int wid = tid >> 5, lane = tid & 31;
    const int g4 = lane >> 2, t4 = lane & 3;
    const int base = blockIdx.x * BPC;
    const int bme = tid & 63;            // epilogue batch row
    const int jg  = tid >> 6;            // epilogue j-group (8 j's), 0..7

    // ---- zero state buffers ----
    for (int i = tid; i < 2816; i += TPB) {
        ((u32*)(sm + SB_SHI))[i] = 0u;
        ((u32*)(sm + SB_SLO))[i] = 0u;
    }
    __syncthreads();
    // x0 + "one" at k=73
    if (tid < BPC) {
        #pragma unroll
        for (int k = 0; k < IN_; k++) {
            float v = src[(size_t)(base + tid) * (SRCLEN * IN_) + k];
            float vh = bfhi(v);
            *(__nv_bfloat16*)(sm + SB_SHI + tid * 176 + (64 + k) * 2) = __float2bfloat16(vh);
            *(__nv_bfloat16*)(sm + SB_SLO + tid * 176 + (64 + k) * 2) = __float2bfloat16(v - vh);
        }
        *(__nv_bfloat16*)(sm + SB_SHI + tid * 176 + 73 * 2) = __float2bfloat16(1.0f);
    }

    u32 ah[5][4], al[5][4];
    load_A(ah, al, eWih, eWhh, eb, wid, lane);

    float cc[8];
    #pragma unroll
    for (int i = 0; i < 8; i++) cc[i] = 0.0f;
    __syncthreads();

    #pragma unroll 1
    for (int t = 0; t < NSTEPS; t++) {
        const bool dec = (t >= SRCLEN);

        // encoder: prefetch next x early (hidden under MMA)
        float xr[IN_];
        if (t < SRCLEN - 1 && tid < BPC) {
            #pragma unroll
            for (int k = 0; k < IN_; k++)
                xr[k] = src[(size_t)(base + tid) * (SRCLEN * IN_) + (t + 1) * IN_ + k];
        }

        // ---- phase A: MMA (warp owns M-tile wid; loop over 8 n-tiles) ----
        const int boff = g4 * 176 + (2 * t4) * 2;
        #pragma unroll
        for (int nt = 0; nt < 8; nt++) {
            u32 bh[5][2], bl[5][2];
            const char* ph = sm + SB_SHI + nt * 8 * 176 + boff;
            const char* pl = sm + SB_SLO + nt * 8 * 176 + boff;
            #pragma unroll
            for (int kc = 0; kc < 5; kc++) {
                bh[kc][0] = *(const u32*)(ph + kc * 32);
                bh[kc][1] = *(const u32*)(ph + kc * 32 + 16);
                bl[kc][0] = *(const u32*)(pl + kc * 32);
                bl[kc][1] = *(const u32*)(pl + kc * 32 + 16);
            }
            float d0[4] = {0.f, 0.f, 0.f, 0.f};
            float d1[4] = {0.f, 0.f, 0.f, 0.f};
            float d2[4] = {0.f, 0.f, 0.f, 0.f};
            #pragma unroll
            for (int kc = 0; kc < 5; kc++) {
                MMA4(d0, ah[kc], bh[kc][0], bh[kc][1]);
                MMA4(d1, ah[kc], bl[kc][0], bl[kc][1]);
                MMA4(d2, al[kc], bh[kc][0], bh[kc][1]);
            }
            int row = 16 * wid + g4;
            int col = 8 * nt + 2 * t4;
            *(float2*)(sm + SB_G + (size_t)row * 272 + col * 4) =
                make_float2(d0[0] + d1[0] + d2[0], d0[1] + d1[1] + d2[1]);
            *(float2*)(sm + SB_G + (size_t)(row + 8) * 272 + col * 4) =
                make_float2(d0[2] + d1[2] + d2[2], d0[3] + d1[3] + d2[3]);
        }
        __syncthreads();   // (1) gates visible; state reads done

        // ---- phase B: activations, c/h update (8 j's per thread) ----
        const float* gr = (const float*)(sm + SB_G);
        float hloc[8];
        #pragma unroll
        for (int jj = 0; jj < 8; jj++) {
            int j = jg * 8 + jj;
            float gi = gr[(4 * j + 0) * 68 + bme];
            float gf = gr[(4 * j + 1) * 68 + bme];
            float gg = gr[(4 * j + 2) * 68 + bme];
            float go = gr[(4 * j + 3) * 68 + bme];
            float ii = fast_sigmoid(gi);
            float ff = fast_sigmoid(gf);
            float g_ = fast_tanh(gg);
            float oo = fast_sigmoid(go);
            float cn = fmaf(ff, cc[jj], ii * g_);
            cc[jj] = cn;
            hloc[jj] = oo * fast_tanh(cn);
        }
        // h -> state buf (hi/lo pairs)
        #pragma unroll
        for (int p = 0; p < 4; p++) {
            int j0 = jg * 8 + 2 * p;
            u32 hw, lw; split2(hloc[2 * p], hloc[2 * p + 1], hw, lw);
            *(u32*)(sm + SB_SHI + bme * 176 + j0 * 2) = hw;
            *(u32*)(sm + SB_SLO + bme * 176 + j0 * 2) = lw;
        }
        // encoder next-x write
        if (t < SRCLEN - 1 && tid < BPC) {
            #pragma unroll
            for (int k = 0; k < IN_; k++) {
                float vh = bfhi(xr[k]);
                *(__nv_bfloat16*)(sm + SB_SHI + tid * 176 + (64 + k) * 2) = __float2bfloat16(vh);
                *(__nv_bfloat16*)(sm + SB_SLO + tid * 176 + (64 + k) * 2) = __float2bfloat16(xr[k] - vh);
            }
        }
        // decoder: distributed FC partials (this thread's 8 h's)
        if (dec) {
            const float* fw = (const float*)(sm + SB_FCW);
            float pa[IN_];
            #pragma unroll
            for (int m = 0; m < IN_; m++) pa[m] = 0.0f;
            #pragma unroll
            for (int jj = 0; jj < 8; jj++) {
                float hv = hloc[jj]; int j = jg * 8 + jj;
                #pragma unroll
                for (int m = 0; m < IN_; m++) pa[m] = fmaf(hv, fw[m * 64 + j], pa[m]);
            }
            float* pb = (float*)(sm + SB_P);
            #pragma unroll
            for (int m = 0; m < IN_; m++) pb[bme * 72 + jg * 9 + m] = pa[m];
        }
        __syncthreads();   // (2) h/x/partials ready

        if (dec) {
            if (tid < BPC) {
                const float* pb = (const float*)(sm + SB_P);
                const float* fb = (const float*)(sm + SB_FCB);
                #pragma unroll
                for (int m = 0; m < IN_; m++) {
                    float pr = fb[m];
                    #pragma unroll
                    for (int q = 0; q < 8; q++) pr += pb[tid * 72 + q * 9 + m];
                    out[(size_t)(base + tid) * (PREDLEN * IN_) + (t - SRCLEN) * IN_ + m] = pr;
                    float ph2 = bfhi(pr);
                    *(__nv_bfloat16*)(sm + SB_SHI + tid * 176 + (64 + m) * 2) = __float2bfloat16(ph2);
                    *(__nv_bfloat16*)(sm + SB_SLO + tid * 176 + (64 + m) * 2) = __float2bfloat16(pr - ph2);
                }
            }
            __syncthreads();   // (3) next x ready
        }

        if (t == SRCLEN - 1) {   // swap to decoder weights + FC into smem
            load_A(ah, al, dWih, dWhh, db, wid, lane);
            for (int i = tid; i < IN_ * H_; i += TPB) ((float*)(sm + SB_FCW))[i] = fcW[i];
            if (tid < IN_) ((float*)(sm + SB_FCB))[tid] = fcb[tid];
            __syncthreads();
        }
    }
}

extern "C" void kernel_launch(void* const* d_in, const int* in_sizes, int n_in,
                              void* d_out, int out_size)
{
    cudaFuncSetAttribute(lstm_mma, cudaFuncAttributeMaxDynamicSharedMemorySize, SMEM_BYTES);
    lstm_mma<<<GRID, TPB, SMEM_BYTES>>>(
        (const float*)d_in[0], (const float*)d_in[1], (const float*)d_in[2],
        (const float*)d_in[3], (const float*)d_in[4], (const float*)d_in[5],
        (const float*)d_in[6], (const float*)d_in[7], (const float*)d_in[8],
        (float*)d_out);
}

// round 14
// speedup vs baseline: 1.0142x; 1.0142x over previous
#include <cuda_runtime.h>
#include <cuda_bf16.h>
#include <cstdint>

// LSTM seq2seq via mma.sync (HMMA bf16, portable sm_103):
//   gates[256, 64b] = W[256, 80] @ state[64b, 80]^T, hi/lo bf16 split (3 passes)
// R14 = R11 (proven) + 3 independent accumulator chains per (nt, i).

#define SRCLEN 7
#define PREDLEN 10
#define NSTEPS 17
#define IN_ 9
#define H_ 64
#define TPB 256
#define BPC 64          // batch rows per CTA
#define GRID 1024

// smem layout (bytes)
#define SB_SHI 0                         // state hi: 64 rows x 88 bf16 (176B)
#define SB_SLO 11264                     // state lo
#define SB_G   22528                     // gate buf: 256 rows x 68 f32 (272B)
#define SB_FCW (22528 + 69632)           // 92160: fc weights 9x64 f32
#define SB_FCB (SB_FCW + 2304)           // 94464
#define SB_P   (SB_FCB + 64)             // 94528: FC partials 64 x 36 f32 (144B)
#define SMEM_BYTES (SB_P + 9216)         // 103744

typedef unsigned int u32;

__device__ __forceinline__ float fast_tanh(float x) {
    float y; asm("tanh.approx.f32 %0, %1;" : "=f"(y) : "f"(x)); return y;
}
__device__ __forceinline__ float fast_sigmoid(float x) { return fmaf(0.5f, fast_tanh(0.5f * x), 0.5f); }
__device__ __forceinline__ u32 pk(float a, float b) {
    __nv_bfloat162 t = __floats2bfloat162_rn(a, b); return *reinterpret_cast<u32*>(&t);
}
__device__ __forceinline__ float bfhi(float v) { return __bfloat162float(__float2bfloat16(v)); }
__device__ __forceinline__ void split2(float a, float b, u32 &hi, u32 &lo) {
    float ah = bfhi(a), bh = bfhi(b);
    hi = pk(a, b); lo = pk(a - ah, b - bh);
}

#define MMA4(d, a, b0, b1) asm volatile( \
    "mma.sync.aligned.m16n8k16.row.col.f32.bf16.bf16.f32 " \
    "{%0,%1,%2,%3},{%4,%5,%6,%7},{%8,%9},{%0,%1,%2,%3};" \
    : "+f"((d)[0]), "+f"((d)[1]), "+f"((d)[2]), "+f"((d)[3]) \
    : "r"((a)[0]), "r"((a)[1]), "r"((a)[2]), "r"((a)[3]), "r"(b0), "r"(b1))

// fused weight element: row m = 4j+g -> source row wr = g*64+j
__device__ __forceinline__ float welem(const float* __restrict__ Wih,
                                       const float* __restrict__ Whh,
                                       const float* __restrict__ bias, int m, int k) {
    int j = m >> 2, g = m & 3, wr = g * 64 + j;
    if (k < 64) return Whh[wr * 64 + k];
    if (k < 73) return Wih[wr * 9 + (k - 64)];
    if (k == 73) return bias[wr];
    return 0.0f;
}

// Load A fragments: warp owns M-tiles {2w, 2w+1}; per tile 5 K-chunks x 4 regs.
// m16n8k16 A frag: q0:(r, k0), q1:(r+8, k0), q2:(r, k0+8), q3:(r+8, k0+8);
// r = lane/4, k0 = 2*(lane%4), each reg = 2 bf16 along k.
__device__ void load_A(u32 ah[2][5][4], u32 al[2][5][4],
                       const float* __restrict__ Wih, const float* __restrict__ Whh,
                       const float* __restrict__ bias, int wid, int lane) {
    int g4 = lane >> 2, t4 = lane & 3;
    #pragma unroll
    for (int i = 0; i < 2; i++) {
        int mt = wid * 2 + i;
        #pragma unroll
        for (int kc = 0; kc < 5; kc++)
            #pragma unroll
            for (int q = 0; q < 4; q++) {
                int m = 16 * mt + g4 + (q & 1) * 8;
                int k = 16 * kc + 2 * t4 + (q >> 1) * 8;
                float v0 = welem(Wih, Whh, bias, m, k);
                float v1 = welem(Wih, Whh, bias, m, k + 1);
                split2(v0, v1, ah[i][kc][q], al[i][kc][q]);
            }
    }
}

__global__ void __launch_bounds__(TPB, 1)
lstm_mma(const float* __restrict__ src,
         const float* __restrict__ eWih, const float* __restrict__ eWhh, const float* __restrict__ eb,
         const float* __restrict__ dWih, const float* __restrict__ dWhh, const float* __restrict__ db,
         const float* __restrict__ fcW, const float* __restrict__ fcb, float* __restrict__ out)
{
    extern __shared__ char sm[];
    const int tid = threadIdx.x;
    const int wid = tid >> 5, lane = tid & 31;
    const int g4 = lane >> 2, t4 = lane & 3;
    const int base = blockIdx.x * BPC;
    const int bme = tid & 63;            // epilogue batch row
    const int jg  = tid >> 6;            // epilogue j-group (16 j's)

    // ---- zero state buffers ----
    for (int i = tid; i < 2816; i += TPB) {
        ((u32*)(sm + SB_SHI))[i] = 0u;
        ((u32*)(sm + SB_SLO))[i] = 0u;
    }
    __syncthreads();
    // x0 + "one" at k=73
    if (tid < BPC) {
        #pragma unroll
        for (int k = 0; k < IN_; k++) {
            float v = src[(size_t)(base + tid) * (SRCLEN * IN_) + k];
            float vh = bfhi(v);
            *(__nv_bfloat16*)(sm + SB_SHI + tid * 176 + (64 + k) * 2) = __float2bfloat16(vh);
            *(__nv_bfloat16*)(sm + SB_SLO + tid * 176 + (64 + k) * 2) = __float2bfloat16(v - vh);
        }
        *(__nv_bfloat16*)(sm + SB_SHI + tid * 176 + 73 * 2) = __float2bfloat16(1.0f);
    }

    u32 ah[2][5][4], al[2][5][4];
    load_A(ah, al, eWih, eWhh, eb, wid, lane);

    float cc[16];
    #pragma unroll
    for (int i = 0; i < 16; i++) cc[i] = 0.0f;
    __syncthreads();

    #pragma unroll 1
    for (int t = 0; t < NSTEPS; t++) {
        const bool dec = (t >= SRCLEN);

        // encoder: prefetch next x early (latency hidden under MMA)
        float xr[IN_];
        if (t < SRCLEN - 1 && tid < BPC) {
            #pragma unroll
            for (int k = 0; k < IN_; k++)
                xr[k] = src[(size_t)(base + tid) * (SRCLEN * IN_) + (t + 1) * IN_ + k];
        }

        // ---- phase A: MMA ----
        const int boff = (g4) * 176 + (2 * t4) * 2;   // + nt*8*176 + kc*32
        #pragma unroll
        for (int nt = 0; nt < 8; nt++) {
            u32 bh[5][2], bl[5][2];
            const char* ph = sm + SB_SHI + nt * 8 * 176 + boff;
            const char* pl = sm + SB_SLO + nt * 8 * 176 + boff;
            #pragma unroll
            for (int kc = 0; kc < 5; kc++) {
                bh[kc][0] = *(const u32*)(ph + kc * 32);
                bh[kc][1] = *(const u32*)(ph + kc * 32 + 16);
                bl[kc][0] = *(const u32*)(pl + kc * 32);
                bl[kc][1] = *(const u32*)(pl + kc * 32 + 16);
            }
            #pragma unroll
            for (int i = 0; i < 2; i++) {
                float d0[4] = {0.f, 0.f, 0.f, 0.f};
                float d1[4] = {0.f, 0.f, 0.f, 0.f};
                float d2[4] = {0.f, 0.f, 0.f, 0.f};
                #pragma unroll
                for (int kc = 0; kc < 5; kc++) {
                    MMA4(d0, ah[i][kc], bh[kc][0], bh[kc][1]);
                    MMA4(d1, ah[i][kc], bl[kc][0], bl[kc][1]);
                    MMA4(d2, al[i][kc], bh[kc][0], bh[kc][1]);
                }
                int row = 16 * (2 * wid + i) + g4;
                int col = 8 * nt + 2 * t4;
                *(float2*)(sm + SB_G + (size_t)row * 272 + col * 4) =
                    make_float2(d0[0] + d1[0] + d2[0], d0[1] + d1[1] + d2[1]);
                *(float2*)(sm + SB_G + (size_t)(row + 8) * 272 + col * 4) =
                    make_float2(d0[2] + d1[2] + d2[2], d0[3] + d1[3] + d2[3]);
            }
        }
        __syncthreads();   // (1) gates visible; state reads done

        // ---- phase B: activations, c/h update ----
        const float* gr = (const float*)(sm + SB_G);
        float hloc[16];
        #pragma unroll
        for (int jj = 0; jj < 16; jj++) {
            int j = jg * 16 + jj;
            float gi = gr[(4 * j + 0) * 68 + bme];
            float gf = gr[(4 * j + 1) * 68 + bme];
            float gg = gr[(4 * j + 2) * 68 + bme];
            float go = gr[(4 * j + 3) * 68 + bme];
            float ii = fast_sigmoid(gi);
            float ff = fast_sigmoid(gf);
            float g_ = fast_tanh(gg);
            float oo = fast_sigmoid(go);
            float cn = fmaf(ff, cc[jj], ii * g_);
            cc[jj] = cn;
            hloc[jj] = oo * fast_tanh(cn);
        }
        // h -> state buf (hi/lo pairs)
        #pragma unroll
        for (int p = 0; p < 8; p++) {
            int j0 = jg * 16 + 2 * p;
            u32 hw, lw; split2(hloc[2 * p], hloc[2 * p + 1], hw, lw);
            *(u32*)(sm + SB_SHI + bme * 176 + j0 * 2) = hw;
            *(u32*)(sm + SB_SLO + bme * 176 + j0 * 2) = lw;
        }
        // encoder next-x write
        if (t < SRCLEN - 1 && tid < BPC) {
            #pragma unroll
            for (int k = 0; k < IN_; k++) {
                float vh = bfhi(xr[k]);
                *(__nv_bfloat16*)(sm + SB_SHI + tid * 176 + (64 + k) * 2) = __float2bfloat16(vh);
                *(__nv_bfloat16*)(sm + SB_SLO + tid * 176 + (64 + k) * 2) = __float2bfloat16(xr[k] - vh);
            }
        }
        // decoder: distributed FC partials (over this thread's 16 h's)
        if (dec) {
            const float* fw = (const float*)(sm + SB_FCW);
            float pa[IN_];
            #pragma unroll
            for (int m = 0; m < IN_; m++) pa[m] = 0.0f;
            #pragma unroll
            for (int jj = 0; jj < 16; jj++) {
                float hv = hloc[jj]; int j = jg * 16 + jj;
                #pragma unroll
                for (int m = 0; m < IN_; m++) pa[m] = fmaf(hv, fw[m * 64 + j], pa[m]);
            }
            float* pb = (float*)(sm + SB_P);
            #pragma unroll
            for (int m = 0; m < IN_; m++) pb[bme * 36 + jg * 9 + m] = pa[m];
        }
        __syncthreads();   // (2) h/x/partials ready

        if (dec) {
            if (tid < BPC) {
                const float* pb = (const float*)(sm + SB_P);
                const float* fb = (const float*)(sm + SB_FCB);
                #pragma unroll
                for (int m = 0; m < IN_; m++) {
                    float pr = fb[m] + pb[tid * 36 + m] + pb[tid * 36 + 9 + m]
                             + pb[tid * 36 + 18 + m] + pb[tid * 36 + 27 + m];
                    out[(size_t)(base + tid) * (PREDLEN * IN_) + (t - SRCLEN) * IN_ + m] = pr;
                    float ph2 = bfhi(pr);
                    *(__nv_bfloat16*)(sm + SB_SHI + tid * 176 + (64 + m) * 2) = __float2bfloat16(ph2);
                    *(__nv_bfloat16*)(sm + SB_SLO + tid * 176 + (64 + m) * 2) = __float2bfloat16(pr - ph2);
                }
            }
            __syncthreads();   // (3) next x ready
        }

        if (t == SRCLEN - 1) {   // swap to decoder weights + FC into smem
            load_A(ah, al, dWih, dWhh, db, wid, lane);
            for (int i = tid; i < IN_ * H_; i += TPB) ((float*)(sm + SB_FCW))[i] = fcW[i];
            if (tid < IN_) ((float*)(sm + SB_FCB))[tid] = fcb[tid];
            __syncthreads();
        }
    }
}

extern "C" void kernel_launch(void* const* d_in, const int* in_sizes, int n_in,
                              void* d_out, int out_size)
{
    cudaFuncSetAttribute(lstm_mma, cudaFuncAttributeMaxDynamicSharedMemorySize, SMEM_BYTES);
    lstm_mma<<<GRID, TPB, SMEM_BYTES>>>(
        (const float*)d_in[0], (const float*)d_in[1], (const float*)d_in[2],
        (const float*)d_in[3], (const float*)d_in[4], (const float*)d_in[5],
        (const float*)d_in[6], (const float*)d_in[7], (const float*)d_in[8],
        (float*)d_out);
}

// round 17
// speedup vs baseline: 1.2351x; 1.2178x over previous
#include <cuda_runtime.h>
#include <cuda_bf16.h>
#include <cstdint>

// LSTM seq2seq via mma.sync m16n8k8 tf32 (portable sm_103), SINGLE pass:
//   gates[256, 64b] = W[256, 80] @ state[64b, 80]^T
// tf32 quantization (2^-11) on W and state; predicted rel_err ~3e-4 < 1e-3.
// R15 = R11 shape (TPB 256, warp = 2 M-tiles, 8 n-tiles) with 33% fewer MMAs.

#define SRCLEN 7
#define PREDLEN 10
#define NSTEPS 17
#define IN_ 9
#define H_ 64
#define TPB 256
#define BPC 64          // batch rows per CTA
#define GRID 1024

// smem layout (bytes)
#define SB_S   0                         // state: 64 rows x 88 f32 (352B), tf32 bits
#define SB_G   22528                     // gate buf: 256 rows x 68 f32 (272B)
#define SB_FCW (22528 + 69632)           // 92160: fc weights 9x64 f32
#define SB_FCB (SB_FCW + 2304)           // 94464
#define SB_P   (SB_FCB + 64)             // 94528: FC partials 64 x 36 f32
#define SMEM_BYTES (SB_P + 9216)         // 103744

typedef unsigned int u32;

__device__ __forceinline__ float fast_tanh(float x) {
    float y; asm("tanh.approx.f32 %0, %1;" : "=f"(y) : "f"(x)); return y;
}
__device__ __forceinline__ float fast_sigmoid(float x) { return fmaf(0.5f, fast_tanh(0.5f * x), 0.5f); }
__device__ __forceinline__ u32 to_tf32(float x) {
    u32 r; asm("cvt.rna.tf32.f32 %0, %1;" : "=r"(r) : "f"(x)); return r;
}

#define MMAT(d, a, b0, b1) asm volatile( \
    "mma.sync.aligned.m16n8k8.row.col.f32.tf32.tf32.f32 " \
    "{%0,%1,%2,%3},{%4,%5,%6,%7},{%8,%9},{%0,%1,%2,%3};" \
    : "+f"((d)[0]), "+f"((d)[1]), "+f"((d)[2]), "+f"((d)[3]) \
    : "r"((a)[0]), "r"((a)[1]), "r"((a)[2]), "r"((a)[3]), "r"(b0), "r"(b1))

// fused weight element: row m = 4j+g -> source row wr = g*64+j
__device__ __forceinline__ float welem(const float* __restrict__ Wih,
                                       const float* __restrict__ Whh,
                                       const float* __restrict__ bias, int m, int k) {
    int j = m >> 2, g = m & 3, wr = g * 64 + j;
    if (k < 64) return Whh[wr * 64 + k];
    if (k < 73) return Wih[wr * 9 + (k - 64)];
    if (k == 73) return bias[wr];
    return 0.0f;
}

// A fragments (tf32 m16n8k8): warp owns M-tiles {2w, 2w+1}; 10 K-chunks x 4 regs.
// a0:(r, k0) a1:(r+8, k0) a2:(r, k0+4) a3:(r+8, k0+4); r = lane/4, k0 = lane%4.
__device__ void load_A(u32 a[2][10][4],
                       const float* __restrict__ Wih, const float* __restrict__ Whh,
                       const float* __restrict__ bias, int wid, int lane) {
    int g4 = lane >> 2, t4 = lane & 3;
    #pragma unroll
    for (int i = 0; i < 2; i++) {
        int mt = wid * 2 + i;
        #pragma unroll
        for (int kc = 0; kc < 10; kc++)
            #pragma unroll
            for (int q = 0; q < 4; q++) {
                int m = 16 * mt + g4 + (q & 1) * 8;
                int k = 8 * kc + t4 + (q >> 1) * 4;
                a[i][kc][q] = to_tf32(welem(Wih, Whh, bias, m, k));
            }
    }
}

__global__ void __launch_bounds__(TPB, 1)
lstm_mma(const float* __restrict__ src,
         const float* __restrict__ eWih, const float* __restrict__ eWhh, const float* __restrict__ eb,
         const float* __restrict__ dWih, const float* __restrict__ dWhh, const float* __restrict__ db,
         const float* __restrict__ fcW, const float* __restrict__ fcb, float* __restrict__ out)
{
    extern __shared__ char sm[];
    const int tid = threadIdx.x;
    const int wid = tid >> 5, lane = tid & 31;
    const int g4 = lane >> 2, t4 = lane & 3;
    const int base = blockIdx.x * BPC;
    const int bme = tid & 63;            // epilogue batch row
    const int jg  = tid >> 6;            // epilogue j-group (16 j's)

    // ---- zero state buffer (64 x 88 f32) ----
    for (int i = tid; i < 5632; i += TPB) ((u32*)(sm + SB_S))[i] = 0u;
    __syncthreads();
    // x0 + "one" at k=73
    if (tid < BPC) {
        u32* srow = (u32*)(sm + SB_S + tid * 352);
        #pragma unroll
        for (int k = 0; k < IN_; k++)
            srow[64 + k] = to_tf32(src[(size_t)(base + tid) * (SRCLEN * IN_) + k]);
        srow[73] = to_tf32(1.0f);
    }

    u32 af[2][10][4];
    load_A(af, eWih, eWhh, eb, wid, lane);

    float cc[16];
    #pragma unroll
    for (int i = 0; i < 16; i++) cc[i] = 0.0f;
    __syncthreads();

    #pragma unroll 1
    for (int t = 0; t < NSTEPS; t++) {
        const bool dec = (t >= SRCLEN);

        // encoder: prefetch next x early (latency hidden under MMA)
        float xr[IN_];
        if (t < SRCLEN - 1 && tid < BPC) {
            #pragma unroll
            for (int k = 0; k < IN_; k++)
                xr[k] = src[(size_t)(base + tid) * (SRCLEN * IN_) + (t + 1) * IN_ + k];
        }

        // ---- phase A: MMA ----
        // B frag: b0 = S[n][kc*8 + t4], b1 = S[n][kc*8 + t4 + 4]; n = nt*8 + g4
        const int boff = g4 * 352 + t4 * 4;
        #pragma unroll
        for (int nt = 0; nt < 8; nt++) {
            u32 b0[10], b1[10];
            const char* pS = sm + SB_S + nt * 8 * 352 + boff;
            #pragma unroll
            for (int kc = 0; kc < 10; kc++) {
                b0[kc] = *(const u32*)(pS + kc * 32);
                b1[kc] = *(const u32*)(pS + kc * 32 + 16);
            }
            #pragma unroll
            for (int i = 0; i < 2; i++) {
                float d0[4] = {0.f, 0.f, 0.f, 0.f};
                float d1[4] = {0.f, 0.f, 0.f, 0.f};
                #pragma unroll
                for (int kc = 0; kc < 5; kc++) {
                    MMAT(d0, af[i][2 * kc],     b0[2 * kc],     b1[2 * kc]);
                    MMAT(d1, af[i][2 * kc + 1], b0[2 * kc + 1], b1[2 * kc + 1]);
                }
                int row = 16 * (2 * wid + i) + g4;
                int col = 8 * nt + 2 * t4;
                *(float2*)(sm + SB_G + (size_t)row * 272 + col * 4) =
                    make_float2(d0[0] + d1[0], d0[1] + d1[1]);
                *(float2*)(sm + SB_G + (size_t)(row + 8) * 272 + col * 4) =
                    make_float2(d0[2] + d1[2], d0[3] + d1[3]);
            }
        }
        __syncthreads();   // (1) gates visible; state reads done

        // ---- phase B: activations, c/h update ----
        const float* gr = (const float*)(sm + SB_G);
        float hloc[16];
        #pragma unroll
        for (int jj = 0; jj < 16; jj++) {
            int j = jg * 16 + jj;
            float gi = gr[(4 * j + 0) * 68 + bme];
            float gf = gr[(4 * j + 1) * 68 + bme];
            float gg = gr[(4 * j + 2) * 68 + bme];
            float go = gr[(4 * j + 3) * 68 + bme];
            float ii = fast_sigmoid(gi);
            float ff = fast_sigmoid(gf);
            float g_ = fast_tanh(gg);
            float oo = fast_sigmoid(go);
            float cn = fmaf(ff, cc[jj], ii * g_);
            cc[jj] = cn;
            hloc[jj] = oo * fast_tanh(cn);
        }
        // h -> state buf (tf32-rounded), pairs via 8-byte stores
        {
            u32* srow = (u32*)(sm + SB_S + bme * 352);
            #pragma unroll
            for (int p = 0; p < 8; p++) {
                int j0 = jg * 16 + 2 * p;
                uint2 hv = make_uint2(to_tf32(hloc[2 * p]), to_tf32(hloc[2 * p + 1]));
                *(uint2*)(srow + j0) = hv;
            }
        }
        // encoder next-x write
        if (t < SRCLEN - 1 && tid < BPC) {
            u32* srow = (u32*)(sm + SB_S + tid * 352);
            #pragma unroll
            for (int k = 0; k < IN_; k++) srow[64 + k] = to_tf32(xr[k]);
        }
        // decoder: distributed FC partials (over this thread's 16 h's)
        if (dec) {
            const float* fw = (const float*)(sm + SB_FCW);
            float pa[IN_];
            #pragma unroll
            for (int m = 0; m < IN_; m++) pa[m] = 0.0f;
            #pragma unroll
            for (int jj = 0; jj < 16; jj++) {
                float hv = hloc[jj]; int j = jg * 16 + jj;
                #pragma unroll
                for (int m = 0; m < IN_; m++) pa[m] = fmaf(hv, fw[m * 64 + j], pa[m]);
            }
            float* pb = (float*)(sm + SB_P);
            #pragma unroll
            for (int m = 0; m < IN_; m++) pb[bme * 36 + jg * 9 + m] = pa[m];
        }
        __syncthreads();   // (2) h/x/partials ready

        if (dec) {
            if (tid < BPC) {
                const float* pb = (const float*)(sm + SB_P);
                const float* fb = (const float*)(sm + SB_FCB);
                u32* srow = (u32*)(sm + SB_S + tid * 352);
                #pragma unroll
                for (int m = 0; m < IN_; m++) {
                    float pr = fb[m] + pb[tid * 36 + m] + pb[tid * 36 + 9 + m]
                             + pb[tid * 36 + 18 + m] + pb[tid * 36 + 27 + m];
                    out[(size_t)(base + tid) * (PREDLEN * IN_) + (t - SRCLEN) * IN_ + m] = pr;
                    srow[64 + m] = to_tf32(pr);
                }
            }
            __syncthreads();   // (3) next x ready
        }

        if (t == SRCLEN - 1) {   // swap to decoder weights + FC into smem
            load_A(af, dWih, dWhh, db, wid, lane);
            for (int i = tid; i < IN_ * H_; i += TPB) ((float*)(sm + SB_FCW))[i] = fcW[i];
            if (tid < IN_) ((float*)(sm + SB_FCB))[tid] = fcb[tid];
            __syncthreads();
        }
    }
}

extern "C" void kernel_launch(void* const* d_in, const int* in_sizes, int n_in,
                              void* d_out, int out_size)
{
    cudaFuncSetAttribute(lstm_mma, cudaFuncAttributeMaxDynamicSharedMemorySize, SMEM_BYTES);
    lstm_mma<<<GRID, TPB, SMEM_BYTES>>>(
        (const float*)d_in[0], (const float*)d_in[1], (const float*)d_in[2],
        (const float*)d_in[3], (const float*)d_in[4], (const float*)d_in[5],
        (const float*)d_in[6], (const float*)d_in[7], (const float*)d_in[8],
        (float*)d_out);
}